// round 11
// baseline (speedup 1.0000x reference)
#include <cuda_runtime.h>
#include <cuda_bf16.h>
#include <math.h>
#include <stdint.h>

// Problem constants
#define BATCH 8
#define MCH   63
#define HW    307200
#define NBLK  120         // stats blocks per batch
#define CHUNK 2560        // HW / NBLK
#define SUB   1280
#define NSUB  2           // CHUNK / SUB
#define PPT   5           // 256*5 = 1280
#define NV    16

// pred mma constants
#define NTILES     9       // 8 G-row tiles + 1 w tile (N = 72)
#define KSTEPS     4       // K = 64 channels, 16 per mma
#define BFRAG_SZ   (NTILES * KSTEPS * 32 * 4)   // u32 per batch = 4608
#define PRED_CTAS  150     // per batch; 150 * 2048 px = HW
#define PX_PER_CTA 2048
#define ROUNDS     16      // 2048 / (8 warps * 16 px)

// Scratch (device globals; no allocation allowed)
__device__ float    g_partA[BATCH * NBLK * 4096];
__device__ float    g_partX[BATCH * NBLK * 64];
__device__ float    g_partS[BATCH * NBLK * 2];
__device__ uint32_t g_bfrag[BATCH * BFRAG_SZ];   // per-lane B fragments (hi/lo bf16 pairs)

// ---------------- small helpers ----------------
__device__ __forceinline__ uint32_t pack_bf2(float lo_elem, float hi_elem) {
    uint32_t r;
    asm("cvt.rn.bf16x2.f32 %0, %1, %2;" : "=r"(r) : "f"(hi_elem), "f"(lo_elem));
    return r;
}
__device__ __forceinline__ void mma16816(float* c, const uint32_t* a, uint32_t b0, uint32_t b1) {
    asm volatile(
        "mma.sync.aligned.m16n8k16.row.col.f32.bf16.bf16.f32 "
        "{%0,%1,%2,%3}, {%4,%5,%6,%7}, {%8,%9}, {%0,%1,%2,%3};"
        : "+f"(c[0]), "+f"(c[1]), "+f"(c[2]), "+f"(c[3])
        : "r"(a[0]), "r"(a[1]), "r"(a[2]), "r"(a[3]), "r"(b0), "r"(b1));
}

// ---------------------------------------------------------------------------
// Kernel 1: sparse masked Gram accumulation (double-buffered gather).
// ---------------------------------------------------------------------------
__global__ void __launch_bounds__(256) stats_kernel(const float* __restrict__ bases,
                                                    const float* __restrict__ targets)
{
    const int b   = blockIdx.x / NBLK;
    const int blk = blockIdx.x % NBLK;
    const float* tgb = targets + (size_t)b * HW;
    const float* bs  = bases   + (size_t)b * MCH * HW;

    __shared__ int   pix [SUB];
    __shared__ float yls [SUB];
    __shared__ float bv  [2][NV][64];
    __shared__ float yg  [2][NV];
    __shared__ int   scan[256];

    const int tid = threadIdx.x;
    const int ti  = tid >> 4;
    const int tj  = tid & 15;

    float acc[4][4];
#pragma unroll
    for (int i = 0; i < 4; i++)
#pragma unroll
        for (int j = 0; j < 4; j++) acc[i][j] = 0.f;

    float xty = 0.f, yty = 0.f, ncnt = 0.f;

    for (int s = 0; s < NSUB; s++) {
        const int base = blk * CHUNK + s * SUB;
        const int p0   = base + tid * PPT;

        int cnt = 0;
#pragma unroll
        for (int k = 0; k < PPT; k++) {
            float y = tgb[p0 + k];
            if (isfinite(y)) cnt++;
        }
        scan[tid] = cnt;
        __syncthreads();
        for (int off = 1; off < 256; off <<= 1) {
            int v = (tid >= off) ? scan[tid - off] : 0;
            __syncthreads();
            scan[tid] += v;
            __syncthreads();
        }
        int wo    = scan[tid] - cnt;
        int total = scan[255];
        __syncthreads();

#pragma unroll
        for (int k = 0; k < PPT; k++) {
            float y = tgb[p0 + k];
            if (isfinite(y)) { pix[wo] = p0 + k; yls[wo] = y; wo++; }
        }
        __syncthreads();

        if (tid == 0) ncnt += (float)total;

        const int ng = (total + NV - 1) / NV;

        if (ng > 0) {
#pragma unroll
            for (int r = 0; r < 4; r++) {
                int idx = r * 256 + tid;
                int v = idx >> 6, c = idx & 63;
                float val = 0.f;
                if (v < total)
                    val = (c == 0) ? 1.f : bs[(size_t)(c - 1) * HW + pix[v]];
                bv[0][v][c] = val;
            }
            if (tid < NV) yg[0][tid] = (tid < total) ? yls[tid] : 0.f;
        }
        __syncthreads();

        for (int g = 0; g < ng; g++) {
            const int cur = g & 1;
            if (g + 1 < ng) {
                const int nxt = cur ^ 1;
                const int bnv = (g + 1) * NV;
#pragma unroll
                for (int r = 0; r < 4; r++) {
                    int idx = r * 256 + tid;
                    int v = idx >> 6, c = idx & 63;
                    int gv = bnv + v;
                    float val = 0.f;
                    if (gv < total)
                        val = (c == 0) ? 1.f : bs[(size_t)(c - 1) * HW + pix[gv]];
                    bv[nxt][v][c] = val;
                }
                if (tid < NV) {
                    int gv = bnv + tid;
                    yg[nxt][tid] = (gv < total) ? yls[gv] : 0.f;
                }
            }

            const float4* bv4 = (const float4*)bv[cur];
#pragma unroll
            for (int v = 0; v < NV; v++) {
                float4 R = bv4[v * 16 + ti];
                float4 C = bv4[v * 16 + tj];
                acc[0][0] += R.x * C.x; acc[0][1] += R.x * C.y; acc[0][2] += R.x * C.z; acc[0][3] += R.x * C.w;
                acc[1][0] += R.y * C.x; acc[1][1] += R.y * C.y; acc[1][2] += R.y * C.z; acc[1][3] += R.y * C.w;
                acc[2][0] += R.z * C.x; acc[2][1] += R.z * C.y; acc[2][2] += R.z * C.z; acc[2][3] += R.z * C.w;
                acc[3][0] += R.w * C.x; acc[3][1] += R.w * C.y; acc[3][2] += R.w * C.z; acc[3][3] += R.w * C.w;
            }
            if (tid < 64) {
#pragma unroll
                for (int v = 0; v < NV; v++) xty += bv[cur][v][tid] * yg[cur][v];
            }
            if (tid == 64) {
#pragma unroll
                for (int v = 0; v < NV; v++) yty += yg[cur][v] * yg[cur][v];
            }
            __syncthreads();
        }
        __syncthreads();
    }

    float* pa = g_partA + ((size_t)b * NBLK + blk) * 4096;
#pragma unroll
    for (int i = 0; i < 4; i++)
#pragma unroll
        for (int j = 0; j < 4; j++)
            pa[(ti * 4 + i) * 64 + (tj * 4 + j)] = acc[i][j];
    if (tid < 64)  g_partX[((size_t)b * NBLK + blk) * 64 + tid] = xty;
    if (tid == 64) g_partS[((size_t)b * NBLK + blk) * 2 + 0] = yty;
    if (tid == 0)  g_partS[((size_t)b * NBLK + blk) * 2 + 1] = ncnt;
}

// ---------------------------------------------------------------------------
// Kernel 2: reduce + Cholesky + solves + beta + L^-1 + B-fragment table.
// ---------------------------------------------------------------------------
__global__ void __launch_bounds__(256) solve_kernel(float* __restrict__ out)
{
    const int b   = blockIdx.x;
    const int tid = threadIdx.x;

    __shared__ float A [64 * 65];
    __shared__ float Li[64 * 65];
    __shared__ float xty[64], wv[64], zv[64];
    __shared__ float sc[4];

    for (int e = tid; e < 4096; e += 256) {
        float s = 0.f;
#pragma unroll 4
        for (int k = 0; k < NBLK; k++) s += g_partA[((size_t)b * NBLK + k) * 4096 + e];
        A[(e >> 6) * 65 + (e & 63)] = s;
    }
    if (tid < 64) {
        float s = 0.f;
#pragma unroll 4
        for (int k = 0; k < NBLK; k++) s += g_partX[((size_t)b * NBLK + k) * 64 + tid];
        xty[tid] = s;
    }
    if (tid == 0) {
        float yt = 0.f, n = 0.f;
        for (int k = 0; k < NBLK; k++) {
            yt += g_partS[((size_t)b * NBLK + k) * 2 + 0];
            n  += g_partS[((size_t)b * NBLK + k) * 2 + 1];
        }
        sc[0] = yt; sc[1] = n;
    }
    __syncthreads();

    for (int k = 0; k < 64; k++) {
        if (tid == 0) A[k * 65 + k] = sqrtf(A[k * 65 + k]);
        __syncthreads();
        if (tid > k && tid < 64) A[tid * 65 + k] /= A[k * 65 + k];
        __syncthreads();
        if (tid > k && tid < 64) {
            float l = A[tid * 65 + k];
            for (int i = k + 1; i <= tid; i++) A[tid * 65 + i] -= l * A[i * 65 + k];
        }
        __syncthreads();
    }

    if (tid < 64) zv[tid] = xty[tid];
    __syncthreads();
    for (int k = 0; k < 64; k++) {
        if (tid == k) zv[k] /= A[k * 65 + k];
        __syncthreads();
        if (tid > k && tid < 64) zv[tid] -= A[tid * 65 + k] * zv[k];
        __syncthreads();
    }
    if (tid < 64) wv[tid] = zv[tid];
    __syncthreads();
    for (int k = 63; k >= 0; k--) {
        if (tid == k) wv[k] /= A[k * 65 + k];
        __syncthreads();
        if (tid < k) wv[tid] -= A[k * 65 + tid] * wv[k];
        __syncthreads();
    }

    if (tid == 0) {
        float yt = sc[0], n = sc[1];
        float wx = 0.f, zz = 0.f;
        for (int c = 0; c < 64; c++) { wx += wv[c] * xty[c]; zz += zv[c] * zv[c]; }
        float E = yt - 2.f * wx + zz;
        float beta0 = sqrtf(n), beta = beta0;
        bool done = false;
        for (int it = 0; it < 5; it++) {
            float bn   = n / (E + 64.f / beta);
            bool  conv = fabsf(bn / beta0 - 1.f) < 0.02f;
            if (!done) { beta = bn; beta0 = bn; }
            done = done || conv;
        }
        sc[2] = beta;
    }
    __syncthreads();

    if (tid < 64) {
        const int c = tid;
        for (int k = c; k < 64; k++) {
            float s = (k == c) ? 1.f : 0.f;
            for (int j = c; j < k; j++) s -= A[k * 65 + j] * Li[j * 65 + c];
            Li[k * 65 + c] = s / A[k * 65 + k];
        }
    }
    __syncthreads();

    const float sb = rsqrtf(sc[2]);
    if (tid < 64) out[(size_t)BATCH * HW + (size_t)b * 64 + tid] = wv[tid];

    // ---- B-fragment table: idx = ((nt*4 + ks)*32 + lane)*4 + j ----
    uint32_t* tabb = g_bfrag + (size_t)b * BFRAG_SZ;
    for (int e = tid; e < BFRAG_SZ; e += 256) {
        int j    = e & 3;
        int lane = (e >> 2) & 31;
        int ks   = (e >> 7) & 3;
        int nt   = e >> 9;
        int n    = nt * 8 + (lane >> 2);
        int k0   = ks * 16 + (lane & 3) * 2 + ((j & 1) ? 8 : 0);

        float v0, v1;
        if (n < 64) {
            v0 = (k0     <= n) ? Li[n * 65 + k0]     * sb : 0.f;
            v1 = (k0 + 1 <= n) ? Li[n * 65 + k0 + 1] * sb : 0.f;
        } else if (n == 64) {
            v0 = wv[k0]; v1 = wv[k0 + 1];
        } else {
            v0 = 0.f; v1 = 0.f;
        }
        uint32_t r;
        if ((j >> 1) == 0) {
            r = pack_bf2(v0, v1);                      // hi parts
        } else {
            float h0 = __bfloat162float(__float2bfloat16(v0));
            float h1 = __bfloat162float(__float2bfloat16(v1));
            r = pack_bf2(v0 - h0, v1 - h1);            // lo parts
        }
        tabb[e] = r;
    }
}

// ---------------------------------------------------------------------------
// Kernel 3: pred + var via mma.sync bf16 3-term split.
// All A fragments (4 K-steps) built first (32 front-loaded LDGs -> high MLP),
// then zero tiles of triangular G are skipped STRUCTURALLY: per-literal-nt
// macros with compile-time ks bounds ({1,1,2,2,3,3,4,4} var, 4 for w).
// Every C[] index is a literal -> registers, no local memory.
// ---------------------------------------------------------------------------
#define MMA_TILE(NT, KSMAX) do {                                             \
    _Pragma("unroll")                                                        \
    for (int ks = 0; ks < (KSMAX); ks++) {                                   \
        uint4 q = Bs4[((NT) * 4 + ks) * 32 + lane];                          \
        mma16816(C[NT], Ah[ks], q.x, q.y);   /* hi * hi */                   \
        mma16816(C[NT], Ah[ks], q.z, q.w);   /* hi * lo */                   \
        mma16816(C[NT], Al[ks], q.x, q.y);   /* lo * hi */                   \
    }                                                                        \
} while (0)

__global__ void __launch_bounds__(256) pred_mma_kernel(const float* __restrict__ bases,
                                                       float* __restrict__ out)
{
    __shared__ uint32_t Bsm[BFRAG_SZ];   // 18.4 KB

    const int b    = blockIdx.x / PRED_CTAS;
    const int cta  = blockIdx.x % PRED_CTAS;
    const int tid  = threadIdx.x;
    const int wid  = tid >> 5;
    const int lane = tid & 31;
    const int g    = lane >> 2;
    const int t    = lane & 3;

    {
        const uint32_t* src = g_bfrag + (size_t)b * BFRAG_SZ;
        for (int e = tid; e < BFRAG_SZ; e += 256) Bsm[e] = src[e];
    }
    __syncthreads();
    const uint4* Bs4 = (const uint4*)Bsm;

    const float* bs   = bases + (size_t)b * MCH * HW;
    float* outL = out + (size_t)b * HW;
    float* outV = out + (size_t)BATCH * HW + (size_t)BATCH * 64 + (size_t)b * HW;

    for (int r = 0; r < ROUNDS; r++) {
        const int px0 = cta * PX_PER_CTA + r * 128 + wid * 16;
        const int pA  = px0 + g;
        const int pB  = pA + 8;

        // ---- build ALL A fragments first (32 coalesced LDGs, high MLP) ----
        uint32_t Ah[KSTEPS][4], Al[KSTEPS][4];
#pragma unroll
        for (int ks = 0; ks < KSTEPS; ks++) {
            const int cA = ks * 16 + t * 2;

            float fA0 = (cA == 0) ? 1.f : __ldg(bs + (size_t)(cA - 1) * HW + pA);
            float fA1 = __ldg(bs + (size_t)(cA    ) * HW + pA);
            float fA2 = __ldg(bs + (size_t)(cA + 7) * HW + pA);
            float fA3 = __ldg(bs + (size_t)(cA + 8) * HW + pA);
            float fB0 = (cA == 0) ? 1.f : __ldg(bs + (size_t)(cA - 1) * HW + pB);
            float fB1 = __ldg(bs + (size_t)(cA    ) * HW + pB);
            float fB2 = __ldg(bs + (size_t)(cA + 7) * HW + pB);
            float fB3 = __ldg(bs + (size_t)(cA + 8) * HW + pB);

            Ah[ks][0] = pack_bf2(fA0, fA1);
            Ah[ks][1] = pack_bf2(fB0, fB1);
            Ah[ks][2] = pack_bf2(fA2, fA3);
            Ah[ks][3] = pack_bf2(fB2, fB3);
            float h;
            h = __uint_as_float(Ah[ks][0] << 16);          float lA0 = fA0 - h;
            h = __uint_as_float(Ah[ks][0] & 0xFFFF0000u);  float lA1 = fA1 - h;
            h = __uint_as_float(Ah[ks][1] << 16);          float lB0 = fB0 - h;
            h = __uint_as_float(Ah[ks][1] & 0xFFFF0000u);  float lB1 = fB1 - h;
            h = __uint_as_float(Ah[ks][2] << 16);          float lA2 = fA2 - h;
            h = __uint_as_float(Ah[ks][2] & 0xFFFF0000u);  float lA3 = fA3 - h;
            h = __uint_as_float(Ah[ks][3] << 16);          float lB2 = fB2 - h;
            h = __uint_as_float(Ah[ks][3] & 0xFFFF0000u);  float lB3 = fB3 - h;
            Al[ks][0] = pack_bf2(lA0, lA1);
            Al[ks][1] = pack_bf2(lB0, lB1);
            Al[ks][2] = pack_bf2(lA2, lA3);
            Al[ks][3] = pack_bf2(lB2, lB3);
        }

        float C[NTILES][4];
#pragma unroll
        for (int n = 0; n < NTILES; n++)
#pragma unroll
            for (int q = 0; q < 4; q++) C[n][q] = 0.f;

        // ---- MMA tiles: literal nt, compile-time ks bounds ----
        MMA_TILE(8, 4);   // w tile (full K)
        MMA_TILE(0, 1);
        MMA_TILE(1, 1);
        MMA_TILE(2, 2);
        MMA_TILE(3, 2);
        MMA_TILE(4, 3);
        MMA_TILE(5, 3);
        MMA_TILE(6, 4);
        MMA_TILE(7, 4);

        // ---- epilogue ----
        float vA = 0.f, vB = 0.f;
#pragma unroll
        for (int nt = 0; nt < 8; nt++) {
            vA = fmaf(C[nt][0], C[nt][0], vA);
            vA = fmaf(C[nt][1], C[nt][1], vA);
            vB = fmaf(C[nt][2], C[nt][2], vB);
            vB = fmaf(C[nt][3], C[nt][3], vB);
        }
        vA += __shfl_xor_sync(0xFFFFFFFFu, vA, 1);
        vA += __shfl_xor_sync(0xFFFFFFFFu, vA, 2);
        vB += __shfl_xor_sync(0xFFFFFFFFu, vB, 1);
        vB += __shfl_xor_sync(0xFFFFFFFFu, vB, 2);

        if (t == 0) {
            outL[pA] = C[8][0];
            outL[pB] = C[8][2];
            outV[pA] = vA;
            outV[pB] = vB;
        }
    }
}

// ---------------------------------------------------------------------------
extern "C" void kernel_launch(void* const* d_in, const int* in_sizes, int n_in,
                              void* d_out, int out_size)
{
    const float* bases   = (const float*)d_in[0];
    const float* targets = (const float*)d_in[1];
    if (n_in >= 2 && in_sizes[0] < in_sizes[1]) {
        const float* t = bases; bases = targets; targets = t;
    }
    float* out = (float*)d_out;

    stats_kernel<<<BATCH * NBLK, 256>>>(bases, targets);
    solve_kernel<<<BATCH, 256>>>(out);
    pred_mma_kernel<<<BATCH * PRED_CTAS, 256>>>(bases, out);
}

// round 12
// speedup vs baseline: 1.0033x; 1.0033x over previous
#include <cuda_runtime.h>
#include <cuda_bf16.h>
#include <math.h>
#include <stdint.h>

// Problem constants
#define BATCH 8
#define MCH   63
#define HW    307200
#define NBLK  120         // stats blocks per batch
#define CHUNK 2560        // HW / NBLK
#define SUB   1280
#define NSUB  2           // CHUNK / SUB
#define PPT   5           // 256*5 = 1280
#define NV    16

// pred mma constants
#define NTILES     9       // 8 G-row tiles + 1 w tile (N = 72)
#define KSTEPS     4
#define BFRAG_SZ   (NTILES * KSTEPS * 32 * 4)   // u32 per batch = 4608
#define PRED_CTAS  150     // per batch; 150 * 2048 px = HW
#define PX_PER_CTA 2048
#define ROUNDS     16      // 2048 / (8 warps * 16 px)

// Scratch (device globals; no allocation allowed)
__device__ float    g_partA[BATCH * NBLK * 4096];
__device__ float    g_partX[BATCH * NBLK * 64];
__device__ float    g_partS[BATCH * NBLK * 2];
__device__ uint32_t g_bfrag[BATCH * BFRAG_SZ];   // per-lane B fragments (hi/lo bf16 pairs)

// ---------------- small helpers ----------------
__device__ __forceinline__ uint32_t pack_bf2(float lo_elem, float hi_elem) {
    uint32_t r;
    asm("cvt.rn.bf16x2.f32 %0, %1, %2;" : "=r"(r) : "f"(hi_elem), "f"(lo_elem));
    return r;
}
__device__ __forceinline__ void mma16816(float* c, const uint32_t* a, uint32_t b0, uint32_t b1) {
    asm volatile(
        "mma.sync.aligned.m16n8k16.row.col.f32.bf16.bf16.f32 "
        "{%0,%1,%2,%3}, {%4,%5,%6,%7}, {%8,%9}, {%0,%1,%2,%3};"
        : "+f"(c[0]), "+f"(c[1]), "+f"(c[2]), "+f"(c[3])
        : "r"(a[0]), "r"(a[1]), "r"(a[2]), "r"(a[3]), "r"(b0), "r"(b1));
}

// ---------------------------------------------------------------------------
// Kernel 1: sparse masked Gram accumulation (double-buffered gather).
// ---------------------------------------------------------------------------
__global__ void __launch_bounds__(256) stats_kernel(const float* __restrict__ bases,
                                                    const float* __restrict__ targets)
{
    const int b   = blockIdx.x / NBLK;
    const int blk = blockIdx.x % NBLK;
    const float* tgb = targets + (size_t)b * HW;
    const float* bs  = bases   + (size_t)b * MCH * HW;

    __shared__ int   pix [SUB];
    __shared__ float yls [SUB];
    __shared__ float bv  [2][NV][64];
    __shared__ float yg  [2][NV];
    __shared__ int   scan[256];

    const int tid = threadIdx.x;
    const int ti  = tid >> 4;
    const int tj  = tid & 15;

    float acc[4][4];
#pragma unroll
    for (int i = 0; i < 4; i++)
#pragma unroll
        for (int j = 0; j < 4; j++) acc[i][j] = 0.f;

    float xty = 0.f, yty = 0.f, ncnt = 0.f;

    for (int s = 0; s < NSUB; s++) {
        const int base = blk * CHUNK + s * SUB;
        const int p0   = base + tid * PPT;

        int cnt = 0;
#pragma unroll
        for (int k = 0; k < PPT; k++) {
            float y = tgb[p0 + k];
            if (isfinite(y)) cnt++;
        }
        scan[tid] = cnt;
        __syncthreads();
        for (int off = 1; off < 256; off <<= 1) {
            int v = (tid >= off) ? scan[tid - off] : 0;
            __syncthreads();
            scan[tid] += v;
            __syncthreads();
        }
        int wo    = scan[tid] - cnt;
        int total = scan[255];
        __syncthreads();

#pragma unroll
        for (int k = 0; k < PPT; k++) {
            float y = tgb[p0 + k];
            if (isfinite(y)) { pix[wo] = p0 + k; yls[wo] = y; wo++; }
        }
        __syncthreads();

        if (tid == 0) ncnt += (float)total;

        const int ng = (total + NV - 1) / NV;

        if (ng > 0) {
#pragma unroll
            for (int r = 0; r < 4; r++) {
                int idx = r * 256 + tid;
                int v = idx >> 6, c = idx & 63;
                float val = 0.f;
                if (v < total)
                    val = (c == 0) ? 1.f : bs[(size_t)(c - 1) * HW + pix[v]];
                bv[0][v][c] = val;
            }
            if (tid < NV) yg[0][tid] = (tid < total) ? yls[tid] : 0.f;
        }
        __syncthreads();

        for (int g = 0; g < ng; g++) {
            const int cur = g & 1;
            if (g + 1 < ng) {
                const int nxt = cur ^ 1;
                const int bnv = (g + 1) * NV;
#pragma unroll
                for (int r = 0; r < 4; r++) {
                    int idx = r * 256 + tid;
                    int v = idx >> 6, c = idx & 63;
                    int gv = bnv + v;
                    float val = 0.f;
                    if (gv < total)
                        val = (c == 0) ? 1.f : bs[(size_t)(c - 1) * HW + pix[gv]];
                    bv[nxt][v][c] = val;
                }
                if (tid < NV) {
                    int gv = bnv + tid;
                    yg[nxt][tid] = (gv < total) ? yls[gv] : 0.f;
                }
            }

            const float4* bv4 = (const float4*)bv[cur];
#pragma unroll
            for (int v = 0; v < NV; v++) {
                float4 R = bv4[v * 16 + ti];
                float4 C = bv4[v * 16 + tj];
                acc[0][0] += R.x * C.x; acc[0][1] += R.x * C.y; acc[0][2] += R.x * C.z; acc[0][3] += R.x * C.w;
                acc[1][0] += R.y * C.x; acc[1][1] += R.y * C.y; acc[1][2] += R.y * C.z; acc[1][3] += R.y * C.w;
                acc[2][0] += R.z * C.x; acc[2][1] += R.z * C.y; acc[2][2] += R.z * C.z; acc[2][3] += R.z * C.w;
                acc[3][0] += R.w * C.x; acc[3][1] += R.w * C.y; acc[3][2] += R.w * C.z; acc[3][3] += R.w * C.w;
            }
            if (tid < 64) {
#pragma unroll
                for (int v = 0; v < NV; v++) xty += bv[cur][v][tid] * yg[cur][v];
            }
            if (tid == 64) {
#pragma unroll
                for (int v = 0; v < NV; v++) yty += yg[cur][v] * yg[cur][v];
            }
            __syncthreads();
        }
        __syncthreads();
    }

    float* pa = g_partA + ((size_t)b * NBLK + blk) * 4096;
#pragma unroll
    for (int i = 0; i < 4; i++)
#pragma unroll
        for (int j = 0; j < 4; j++)
            pa[(ti * 4 + i) * 64 + (tj * 4 + j)] = acc[i][j];
    if (tid < 64)  g_partX[((size_t)b * NBLK + blk) * 64 + tid] = xty;
    if (tid == 64) g_partS[((size_t)b * NBLK + blk) * 2 + 0] = yty;
    if (tid == 0)  g_partS[((size_t)b * NBLK + blk) * 2 + 1] = ncnt;
}

// ---------------------------------------------------------------------------
// Kernel 2: reduce + Cholesky + solves + beta + L^-1 + B-fragment table.
// ---------------------------------------------------------------------------
__global__ void __launch_bounds__(256) solve_kernel(float* __restrict__ out)
{
    const int b   = blockIdx.x;
    const int tid = threadIdx.x;

    __shared__ float A [64 * 65];
    __shared__ float Li[64 * 65];
    __shared__ float xty[64], wv[64], zv[64];
    __shared__ float sc[4];

    for (int e = tid; e < 4096; e += 256) {
        float s = 0.f;
#pragma unroll 4
        for (int k = 0; k < NBLK; k++) s += g_partA[((size_t)b * NBLK + k) * 4096 + e];
        A[(e >> 6) * 65 + (e & 63)] = s;
    }
    if (tid < 64) {
        float s = 0.f;
#pragma unroll 4
        for (int k = 0; k < NBLK; k++) s += g_partX[((size_t)b * NBLK + k) * 64 + tid];
        xty[tid] = s;
    }
    if (tid == 0) {
        float yt = 0.f, n = 0.f;
        for (int k = 0; k < NBLK; k++) {
            yt += g_partS[((size_t)b * NBLK + k) * 2 + 0];
            n  += g_partS[((size_t)b * NBLK + k) * 2 + 1];
        }
        sc[0] = yt; sc[1] = n;
    }
    __syncthreads();

    for (int k = 0; k < 64; k++) {
        if (tid == 0) A[k * 65 + k] = sqrtf(A[k * 65 + k]);
        __syncthreads();
        if (tid > k && tid < 64) A[tid * 65 + k] /= A[k * 65 + k];
        __syncthreads();
        if (tid > k && tid < 64) {
            float l = A[tid * 65 + k];
            for (int i = k + 1; i <= tid; i++) A[tid * 65 + i] -= l * A[i * 65 + k];
        }
        __syncthreads();
    }

    if (tid < 64) zv[tid] = xty[tid];
    __syncthreads();
    for (int k = 0; k < 64; k++) {
        if (tid == k) zv[k] /= A[k * 65 + k];
        __syncthreads();
        if (tid > k && tid < 64) zv[tid] -= A[tid * 65 + k] * zv[k];
        __syncthreads();
    }
    if (tid < 64) wv[tid] = zv[tid];
    __syncthreads();
    for (int k = 63; k >= 0; k--) {
        if (tid == k) wv[k] /= A[k * 65 + k];
        __syncthreads();
        if (tid < k) wv[tid] -= A[k * 65 + tid] * wv[k];
        __syncthreads();
    }

    if (tid == 0) {
        float yt = sc[0], n = sc[1];
        float wx = 0.f, zz = 0.f;
        for (int c = 0; c < 64; c++) { wx += wv[c] * xty[c]; zz += zv[c] * zv[c]; }
        float E = yt - 2.f * wx + zz;
        float beta0 = sqrtf(n), beta = beta0;
        bool done = false;
        for (int it = 0; it < 5; it++) {
            float bn   = n / (E + 64.f / beta);
            bool  conv = fabsf(bn / beta0 - 1.f) < 0.02f;
            if (!done) { beta = bn; beta0 = bn; }
            done = done || conv;
        }
        sc[2] = beta;
    }
    __syncthreads();

    if (tid < 64) {
        const int c = tid;
        for (int k = c; k < 64; k++) {
            float s = (k == c) ? 1.f : 0.f;
            for (int j = c; j < k; j++) s -= A[k * 65 + j] * Li[j * 65 + c];
            Li[k * 65 + c] = s / A[k * 65 + k];
        }
    }
    __syncthreads();

    const float sb = rsqrtf(sc[2]);
    if (tid < 64) out[(size_t)BATCH * HW + (size_t)b * 64 + tid] = wv[tid];

    // ---- B-fragment table: idx = ((nt*4 + ks)*32 + lane)*4 + j ----
    uint32_t* tabb = g_bfrag + (size_t)b * BFRAG_SZ;
    for (int e = tid; e < BFRAG_SZ; e += 256) {
        int j    = e & 3;
        int lane = (e >> 2) & 31;
        int ks   = (e >> 7) & 3;
        int nt   = e >> 9;
        int n    = nt * 8 + (lane >> 2);
        int k0   = ks * 16 + (lane & 3) * 2 + ((j & 1) ? 8 : 0);

        float v0, v1;
        if (n < 64) {
            v0 = (k0     <= n) ? Li[n * 65 + k0]     * sb : 0.f;
            v1 = (k0 + 1 <= n) ? Li[n * 65 + k0 + 1] * sb : 0.f;
        } else if (n == 64) {
            v0 = wv[k0]; v1 = wv[k0 + 1];
        } else {
            v0 = 0.f; v1 = 0.f;
        }
        uint32_t r;
        if ((j >> 1) == 0) {
            r = pack_bf2(v0, v1);                      // hi parts
        } else {
            float h0 = __bfloat162float(__float2bfloat16(v0));
            float h1 = __bfloat162float(__float2bfloat16(v1));
            r = pack_bf2(v0 - h0, v1 - h1);            // lo parts
        }
        tabb[e] = r;
    }
}

// ---------------------------------------------------------------------------
// Kernel 3: pred + var via mma.sync bf16 3-term split.
// R9's interleaved per-K-step structure (low register pressure, 2 CTAs/SM)
// + structural triangular zero-tile skip: explicit literal-ks blocks, each
// running only the tiles with nt >= 2*ks. 72 MMAs per 16-px warp tile.
// ---------------------------------------------------------------------------
#define FRAG_LOAD(KS) do {                                                   \
    const int cA = (KS) * 16 + t * 2;                                        \
    float fA0 = ((KS) == 0 && t == 0) ? 1.f : __ldg(bs + (size_t)(cA - 1) * HW + pA); \
    float fA1 = __ldg(bs + (size_t)(cA    ) * HW + pA);                      \
    float fA2 = __ldg(bs + (size_t)(cA + 7) * HW + pA);                      \
    float fA3 = __ldg(bs + (size_t)(cA + 8) * HW + pA);                      \
    float fB0 = ((KS) == 0 && t == 0) ? 1.f : __ldg(bs + (size_t)(cA - 1) * HW + pB); \
    float fB1 = __ldg(bs + (size_t)(cA    ) * HW + pB);                      \
    float fB2 = __ldg(bs + (size_t)(cA + 7) * HW + pB);                      \
    float fB3 = __ldg(bs + (size_t)(cA + 8) * HW + pB);                      \
    Ah[0] = pack_bf2(fA0, fA1);                                              \
    Ah[1] = pack_bf2(fB0, fB1);                                              \
    Ah[2] = pack_bf2(fA2, fA3);                                              \
    Ah[3] = pack_bf2(fB2, fB3);                                              \
    float h;                                                                 \
    h = __uint_as_float(Ah[0] << 16);          float lA0 = fA0 - h;          \
    h = __uint_as_float(Ah[0] & 0xFFFF0000u);  float lA1 = fA1 - h;          \
    h = __uint_as_float(Ah[1] << 16);          float lB0 = fB0 - h;          \
    h = __uint_as_float(Ah[1] & 0xFFFF0000u);  float lB1 = fB1 - h;          \
    h = __uint_as_float(Ah[2] << 16);          float lA2 = fA2 - h;          \
    h = __uint_as_float(Ah[2] & 0xFFFF0000u);  float lA3 = fA3 - h;          \
    h = __uint_as_float(Ah[3] << 16);          float lB2 = fB2 - h;          \
    h = __uint_as_float(Ah[3] & 0xFFFF0000u);  float lB3 = fB3 - h;          \
    Al[0] = pack_bf2(lA0, lA1);                                              \
    Al[1] = pack_bf2(lB0, lB1);                                              \
    Al[2] = pack_bf2(lA2, lA3);                                              \
    Al[3] = pack_bf2(lB2, lB3);                                              \
} while (0)

#define MMA3(NT, KS) do {                                                    \
    uint4 q = Bs4[((NT) * 4 + (KS)) * 32 + lane];                            \
    mma16816(C[NT], Ah, q.x, q.y);   /* hi * hi */                           \
    mma16816(C[NT], Ah, q.z, q.w);   /* hi * lo */                           \
    mma16816(C[NT], Al, q.x, q.y);   /* lo * hi */                           \
} while (0)

__global__ void __launch_bounds__(256) pred_mma_kernel(const float* __restrict__ bases,
                                                       float* __restrict__ out)
{
    __shared__ uint32_t Bsm[BFRAG_SZ];   // 18.4 KB

    const int b    = blockIdx.x / PRED_CTAS;
    const int cta  = blockIdx.x % PRED_CTAS;
    const int tid  = threadIdx.x;
    const int wid  = tid >> 5;
    const int lane = tid & 31;
    const int g    = lane >> 2;
    const int t    = lane & 3;

    {
        const uint32_t* src = g_bfrag + (size_t)b * BFRAG_SZ;
        for (int e = tid; e < BFRAG_SZ; e += 256) Bsm[e] = src[e];
    }
    __syncthreads();
    const uint4* Bs4 = (const uint4*)Bsm;

    const float* bs   = bases + (size_t)b * MCH * HW;
    float* outL = out + (size_t)b * HW;
    float* outV = out + (size_t)BATCH * HW + (size_t)BATCH * 64 + (size_t)b * HW;

    for (int r = 0; r < ROUNDS; r++) {
        const int px0 = cta * PX_PER_CTA + r * 128 + wid * 16;
        const int pA  = px0 + g;
        const int pB  = pA + 8;

        float C[NTILES][4];
#pragma unroll
        for (int n = 0; n < NTILES; n++)
#pragma unroll
            for (int q = 0; q < 4; q++) C[n][q] = 0.f;

        uint32_t Ah[4], Al[4];

        // ks = 0: all tiles live
        FRAG_LOAD(0);
        MMA3(8, 0);
        MMA3(0, 0); MMA3(1, 0); MMA3(2, 0); MMA3(3, 0);
        MMA3(4, 0); MMA3(5, 0); MMA3(6, 0); MMA3(7, 0);

        // ks = 1: tiles nt >= 2
        FRAG_LOAD(1);
        MMA3(8, 1);
        MMA3(2, 1); MMA3(3, 1); MMA3(4, 1); MMA3(5, 1);
        MMA3(6, 1); MMA3(7, 1);

        // ks = 2: tiles nt >= 4
        FRAG_LOAD(2);
        MMA3(8, 2);
        MMA3(4, 2); MMA3(5, 2); MMA3(6, 2); MMA3(7, 2);

        // ks = 3: tiles nt >= 6
        FRAG_LOAD(3);
        MMA3(8, 3);
        MMA3(6, 3); MMA3(7, 3);

        // ---- epilogue ----
        float vA = 0.f, vB = 0.f;
#pragma unroll
        for (int nt = 0; nt < 8; nt++) {
            vA = fmaf(C[nt][0], C[nt][0], vA);
            vA = fmaf(C[nt][1], C[nt][1], vA);
            vB = fmaf(C[nt][2], C[nt][2], vB);
            vB = fmaf(C[nt][3], C[nt][3], vB);
        }
        vA += __shfl_xor_sync(0xFFFFFFFFu, vA, 1);
        vA += __shfl_xor_sync(0xFFFFFFFFu, vA, 2);
        vB += __shfl_xor_sync(0xFFFFFFFFu, vB, 1);
        vB += __shfl_xor_sync(0xFFFFFFFFu, vB, 2);

        if (t == 0) {
            outL[pA] = C[8][0];
            outL[pB] = C[8][2];
            outV[pA] = vA;
            outV[pB] = vB;
        }
    }
}

// ---------------------------------------------------------------------------
extern "C" void kernel_launch(void* const* d_in, const int* in_sizes, int n_in,
                              void* d_out, int out_size)
{
    const float* bases   = (const float*)d_in[0];
    const float* targets = (const float*)d_in[1];
    if (n_in >= 2 && in_sizes[0] < in_sizes[1]) {
        const float* t = bases; bases = targets; targets = t;
    }
    float* out = (float*)d_out;

    stats_kernel<<<BATCH * NBLK, 256>>>(bases, targets);
    solve_kernel<<<BATCH, 256>>>(out);
    pred_mma_kernel<<<BATCH * PRED_CTAS, 256>>>(bases, out);
}

// round 13
// speedup vs baseline: 1.5709x; 1.5658x over previous
#include <cuda_runtime.h>
#include <cuda_bf16.h>
#include <math.h>
#include <stdint.h>

// Problem constants
#define BATCH 8
#define MCH   63
#define HW    307200
#define NBLK  120         // stats blocks per batch
#define CHUNK 2560        // HW / NBLK
#define SUB   1280
#define NSUB  2           // CHUNK / SUB
#define PPT   5           // 256*5 = 1280
#define NV    16

// pred mma constants
#define NTILES     9       // 8 G-row tiles + 1 w tile (N = 72)
#define KSTEPS     4       // K = 64 channels, 16 per mma
#define BFRAG_SZ   (NTILES * KSTEPS * 32 * 4)   // u32 per batch = 4608
#define PRED_CTAS  150     // per batch; 150 * 2048 px = HW
#define PX_PER_CTA 2048
#define ROUNDS     16      // 2048 / (8 warps * 16 px)

// Scratch (device globals; no allocation allowed)
__device__ float    g_partA[BATCH * NBLK * 4096];
__device__ float    g_partX[BATCH * NBLK * 64];
__device__ float    g_partS[BATCH * NBLK * 2];
__device__ float    g_redA[BATCH * 4096];
__device__ float    g_redX[BATCH * 64];
__device__ float    g_redS[BATCH * 2];
__device__ uint32_t g_bfrag[BATCH * BFRAG_SZ];   // per-lane B fragments (hi/lo bf16 pairs)

// ---------------- small helpers ----------------
__device__ __forceinline__ uint32_t pack_bf2(float lo_elem, float hi_elem) {
    uint32_t r;
    asm("cvt.rn.bf16x2.f32 %0, %1, %2;" : "=r"(r) : "f"(hi_elem), "f"(lo_elem));
    return r;
}
__device__ __forceinline__ void mma16816(float* c, const uint32_t* a, uint32_t b0, uint32_t b1) {
    asm volatile(
        "mma.sync.aligned.m16n8k16.row.col.f32.bf16.bf16.f32 "
        "{%0,%1,%2,%3}, {%4,%5,%6,%7}, {%8,%9}, {%0,%1,%2,%3};"
        : "+f"(c[0]), "+f"(c[1]), "+f"(c[2]), "+f"(c[3])
        : "r"(a[0]), "r"(a[1]), "r"(a[2]), "r"(a[3]), "r"(b0), "r"(b1));
}

// ---------------------------------------------------------------------------
// Kernel 1: sparse masked Gram accumulation (double-buffered gather).
// ---------------------------------------------------------------------------
__global__ void __launch_bounds__(256) stats_kernel(const float* __restrict__ bases,
                                                    const float* __restrict__ targets)
{
    const int b   = blockIdx.x / NBLK;
    const int blk = blockIdx.x % NBLK;
    const float* tgb = targets + (size_t)b * HW;
    const float* bs  = bases   + (size_t)b * MCH * HW;

    __shared__ int   pix [SUB];
    __shared__ float yls [SUB];
    __shared__ float bv  [2][NV][64];
    __shared__ float yg  [2][NV];
    __shared__ int   scan[256];

    const int tid = threadIdx.x;
    const int ti  = tid >> 4;
    const int tj  = tid & 15;

    float acc[4][4];
#pragma unroll
    for (int i = 0; i < 4; i++)
#pragma unroll
        for (int j = 0; j < 4; j++) acc[i][j] = 0.f;

    float xty = 0.f, yty = 0.f, ncnt = 0.f;

    for (int s = 0; s < NSUB; s++) {
        const int base = blk * CHUNK + s * SUB;
        const int p0   = base + tid * PPT;

        int cnt = 0;
#pragma unroll
        for (int k = 0; k < PPT; k++) {
            float y = tgb[p0 + k];
            if (isfinite(y)) cnt++;
        }
        scan[tid] = cnt;
        __syncthreads();
        for (int off = 1; off < 256; off <<= 1) {
            int v = (tid >= off) ? scan[tid - off] : 0;
            __syncthreads();
            scan[tid] += v;
            __syncthreads();
        }
        int wo    = scan[tid] - cnt;
        int total = scan[255];
        __syncthreads();

#pragma unroll
        for (int k = 0; k < PPT; k++) {
            float y = tgb[p0 + k];
            if (isfinite(y)) { pix[wo] = p0 + k; yls[wo] = y; wo++; }
        }
        __syncthreads();

        if (tid == 0) ncnt += (float)total;

        const int ng = (total + NV - 1) / NV;

        if (ng > 0) {
#pragma unroll
            for (int r = 0; r < 4; r++) {
                int idx = r * 256 + tid;
                int v = idx >> 6, c = idx & 63;
                float val = 0.f;
                if (v < total)
                    val = (c == 0) ? 1.f : bs[(size_t)(c - 1) * HW + pix[v]];
                bv[0][v][c] = val;
            }
            if (tid < NV) yg[0][tid] = (tid < total) ? yls[tid] : 0.f;
        }
        __syncthreads();

        for (int g = 0; g < ng; g++) {
            const int cur = g & 1;
            if (g + 1 < ng) {
                const int nxt = cur ^ 1;
                const int bnv = (g + 1) * NV;
#pragma unroll
                for (int r = 0; r < 4; r++) {
                    int idx = r * 256 + tid;
                    int v = idx >> 6, c = idx & 63;
                    int gv = bnv + v;
                    float val = 0.f;
                    if (gv < total)
                        val = (c == 0) ? 1.f : bs[(size_t)(c - 1) * HW + pix[gv]];
                    bv[nxt][v][c] = val;
                }
                if (tid < NV) {
                    int gv = bnv + tid;
                    yg[nxt][tid] = (gv < total) ? yls[gv] : 0.f;
                }
            }

            const float4* bv4 = (const float4*)bv[cur];
#pragma unroll
            for (int v = 0; v < NV; v++) {
                float4 R = bv4[v * 16 + ti];
                float4 C = bv4[v * 16 + tj];
                acc[0][0] += R.x * C.x; acc[0][1] += R.x * C.y; acc[0][2] += R.x * C.z; acc[0][3] += R.x * C.w;
                acc[1][0] += R.y * C.x; acc[1][1] += R.y * C.y; acc[1][2] += R.y * C.z; acc[1][3] += R.y * C.w;
                acc[2][0] += R.z * C.x; acc[2][1] += R.z * C.y; acc[2][2] += R.z * C.z; acc[2][3] += R.z * C.w;
                acc[3][0] += R.w * C.x; acc[3][1] += R.w * C.y; acc[3][2] += R.w * C.z; acc[3][3] += R.w * C.w;
            }
            if (tid < 64) {
#pragma unroll
                for (int v = 0; v < NV; v++) xty += bv[cur][v][tid] * yg[cur][v];
            }
            if (tid == 64) {
#pragma unroll
                for (int v = 0; v < NV; v++) yty += yg[cur][v] * yg[cur][v];
            }
            __syncthreads();
        }
        __syncthreads();
    }

    float* pa = g_partA + ((size_t)b * NBLK + blk) * 4096;
#pragma unroll
    for (int i = 0; i < 4; i++)
#pragma unroll
        for (int j = 0; j < 4; j++)
            pa[(ti * 4 + i) * 64 + (tj * 4 + j)] = acc[i][j];
    if (tid < 64)  g_partX[((size_t)b * NBLK + blk) * 64 + tid] = xty;
    if (tid == 64) g_partS[((size_t)b * NBLK + blk) * 2 + 0] = yty;
    if (tid == 0)  g_partS[((size_t)b * NBLK + blk) * 2 + 1] = ncnt;
}

// ---------------------------------------------------------------------------
// Kernel 1.5: PARALLEL partial reduction (was the hidden serial bottleneck
// inside solve_kernel: 8 CTAs streaming 15.7 MB latency-bound).
// grid = BATCH*16 CTAs; each thread reduces one Gram element over NBLK parts.
// ---------------------------------------------------------------------------
__global__ void __launch_bounds__(256) reduce_kernel()
{
    const int b    = blockIdx.x >> 4;
    const int part = blockIdx.x & 15;
    const int e    = part * 256 + threadIdx.x;   // 0..4095

    const float* pa = g_partA + (size_t)b * NBLK * 4096 + e;
    float s = 0.f;
#pragma unroll 8
    for (int k = 0; k < NBLK; k++) s += pa[(size_t)k * 4096];
    g_redA[b * 4096 + e] = s;

    if (part == 0 && threadIdx.x < 64) {
        const float* px = g_partX + (size_t)b * NBLK * 64 + threadIdx.x;
        float sx = 0.f;
#pragma unroll 8
        for (int k = 0; k < NBLK; k++) sx += px[(size_t)k * 64];
        g_redX[b * 64 + threadIdx.x] = sx;
    }
    if (part == 1 && threadIdx.x < 2) {
        const float* ps = g_partS + (size_t)b * NBLK * 2 + threadIdx.x;
        float ss = 0.f;
#pragma unroll 8
        for (int k = 0; k < NBLK; k++) ss += ps[(size_t)k * 2];
        g_redS[b * 2 + threadIdx.x] = ss;
    }
}

// ---------------------------------------------------------------------------
// Kernel 2: Cholesky + solves + beta + L^-1 + B-fragment table (reads the
// pre-reduced Gram matrix; no heavy global streaming here anymore).
// ---------------------------------------------------------------------------
__global__ void __launch_bounds__(256) solve_kernel(float* __restrict__ out)
{
    const int b   = blockIdx.x;
    const int tid = threadIdx.x;

    __shared__ float A [64 * 65];
    __shared__ float Li[64 * 65];
    __shared__ float xty[64], wv[64], zv[64];
    __shared__ float sc[4];

    for (int e = tid; e < 4096; e += 256)
        A[(e >> 6) * 65 + (e & 63)] = g_redA[b * 4096 + e];
    if (tid < 64) xty[tid] = g_redX[b * 64 + tid];
    if (tid == 0) { sc[0] = g_redS[b * 2 + 0]; sc[1] = g_redS[b * 2 + 1]; }
    __syncthreads();

    for (int k = 0; k < 64; k++) {
        if (tid == 0) A[k * 65 + k] = sqrtf(A[k * 65 + k]);
        __syncthreads();
        if (tid > k && tid < 64) A[tid * 65 + k] /= A[k * 65 + k];
        __syncthreads();
        if (tid > k && tid < 64) {
            float l = A[tid * 65 + k];
            for (int i = k + 1; i <= tid; i++) A[tid * 65 + i] -= l * A[i * 65 + k];
        }
        __syncthreads();
    }

    if (tid < 64) zv[tid] = xty[tid];
    __syncthreads();
    for (int k = 0; k < 64; k++) {
        if (tid == k) zv[k] /= A[k * 65 + k];
        __syncthreads();
        if (tid > k && tid < 64) zv[tid] -= A[tid * 65 + k] * zv[k];
        __syncthreads();
    }
    if (tid < 64) wv[tid] = zv[tid];
    __syncthreads();
    for (int k = 63; k >= 0; k--) {
        if (tid == k) wv[k] /= A[k * 65 + k];
        __syncthreads();
        if (tid < k) wv[tid] -= A[k * 65 + tid] * wv[k];
        __syncthreads();
    }

    if (tid == 0) {
        float yt = sc[0], n = sc[1];
        float wx = 0.f, zz = 0.f;
        for (int c = 0; c < 64; c++) { wx += wv[c] * xty[c]; zz += zv[c] * zv[c]; }
        float E = yt - 2.f * wx + zz;
        float beta0 = sqrtf(n), beta = beta0;
        bool done = false;
        for (int it = 0; it < 5; it++) {
            float bn   = n / (E + 64.f / beta);
            bool  conv = fabsf(bn / beta0 - 1.f) < 0.02f;
            if (!done) { beta = bn; beta0 = bn; }
            done = done || conv;
        }
        sc[2] = beta;
    }
    __syncthreads();

    if (tid < 64) {
        const int c = tid;
        for (int k = c; k < 64; k++) {
            float s = (k == c) ? 1.f : 0.f;
            for (int j = c; j < k; j++) s -= A[k * 65 + j] * Li[j * 65 + c];
            Li[k * 65 + c] = s / A[k * 65 + k];
        }
    }
    __syncthreads();

    const float sb = rsqrtf(sc[2]);
    if (tid < 64) out[(size_t)BATCH * HW + (size_t)b * 64 + tid] = wv[tid];

    // ---- B-fragment table: idx = ((nt*4 + ks)*32 + lane)*4 + j ----
    uint32_t* tabb = g_bfrag + (size_t)b * BFRAG_SZ;
    for (int e = tid; e < BFRAG_SZ; e += 256) {
        int j    = e & 3;
        int lane = (e >> 2) & 31;
        int ks   = (e >> 7) & 3;
        int nt   = e >> 9;
        int n    = nt * 8 + (lane >> 2);
        int k0   = ks * 16 + (lane & 3) * 2 + ((j & 1) ? 8 : 0);

        float v0, v1;
        if (n < 64) {
            v0 = (k0     <= n) ? Li[n * 65 + k0]     * sb : 0.f;
            v1 = (k0 + 1 <= n) ? Li[n * 65 + k0 + 1] * sb : 0.f;
        } else if (n == 64) {
            v0 = wv[k0]; v1 = wv[k0 + 1];
        } else {
            v0 = 0.f; v1 = 0.f;
        }
        uint32_t r;
        if ((j >> 1) == 0) {
            r = pack_bf2(v0, v1);                      // hi parts
        } else {
            float h0 = __bfloat162float(__float2bfloat16(v0));
            float h1 = __bfloat162float(__float2bfloat16(v1));
            r = pack_bf2(v0 - h0, v1 - h1);            // lo parts
        }
        tabb[e] = r;
    }
}

// ---------------------------------------------------------------------------
// Kernel 3: pred + var via mma.sync bf16 3-term split — EXACT R9 structure
// (proven fastest pred; interleaved per-K-step loads, low register pressure).
// ---------------------------------------------------------------------------
__global__ void __launch_bounds__(256) pred_mma_kernel(const float* __restrict__ bases,
                                                       float* __restrict__ out)
{
    __shared__ uint32_t Bsm[BFRAG_SZ];   // 18.4 KB

    const int b    = blockIdx.x / PRED_CTAS;
    const int cta  = blockIdx.x % PRED_CTAS;
    const int tid  = threadIdx.x;
    const int wid  = tid >> 5;
    const int lane = tid & 31;
    const int g    = lane >> 2;
    const int t    = lane & 3;

    {
        const uint32_t* src = g_bfrag + (size_t)b * BFRAG_SZ;
        for (int e = tid; e < BFRAG_SZ; e += 256) Bsm[e] = src[e];
    }
    __syncthreads();
    const uint4* Bs4 = (const uint4*)Bsm;

    const float* bs   = bases + (size_t)b * MCH * HW;
    float* outL = out + (size_t)b * HW;
    float* outV = out + (size_t)BATCH * HW + (size_t)BATCH * 64 + (size_t)b * HW;

    for (int r = 0; r < ROUNDS; r++) {
        const int px0 = cta * PX_PER_CTA + r * 128 + wid * 16;
        const int pA  = px0 + g;
        const int pB  = pA + 8;

        float C[NTILES][4];
#pragma unroll
        for (int n = 0; n < NTILES; n++)
#pragma unroll
            for (int q = 0; q < 4; q++) C[n][q] = 0.f;

#pragma unroll
        for (int ks = 0; ks < KSTEPS; ks++) {
            const int cA = ks * 16 + t * 2;

            float fA0 = (cA == 0) ? 1.f : __ldg(bs + (size_t)(cA - 1) * HW + pA);
            float fA1 = __ldg(bs + (size_t)(cA    ) * HW + pA);
            float fA2 = __ldg(bs + (size_t)(cA + 7) * HW + pA);
            float fA3 = __ldg(bs + (size_t)(cA + 8) * HW + pA);
            float fB0 = (cA == 0) ? 1.f : __ldg(bs + (size_t)(cA - 1) * HW + pB);
            float fB1 = __ldg(bs + (size_t)(cA    ) * HW + pB);
            float fB2 = __ldg(bs + (size_t)(cA + 7) * HW + pB);
            float fB3 = __ldg(bs + (size_t)(cA + 8) * HW + pB);

            uint32_t Ah[4], Al[4];
            Ah[0] = pack_bf2(fA0, fA1);
            Ah[1] = pack_bf2(fB0, fB1);
            Ah[2] = pack_bf2(fA2, fA3);
            Ah[3] = pack_bf2(fB2, fB3);
            {
                float h;
                h = __uint_as_float(Ah[0] << 16);          float lA0 = fA0 - h;
                h = __uint_as_float(Ah[0] & 0xFFFF0000u);  float lA1 = fA1 - h;
                h = __uint_as_float(Ah[1] << 16);          float lB0 = fB0 - h;
                h = __uint_as_float(Ah[1] & 0xFFFF0000u);  float lB1 = fB1 - h;
                h = __uint_as_float(Ah[2] << 16);          float lA2 = fA2 - h;
                h = __uint_as_float(Ah[2] & 0xFFFF0000u);  float lA3 = fA3 - h;
                h = __uint_as_float(Ah[3] << 16);          float lB2 = fB2 - h;
                h = __uint_as_float(Ah[3] & 0xFFFF0000u);  float lB3 = fB3 - h;
                Al[0] = pack_bf2(lA0, lA1);
                Al[1] = pack_bf2(lB0, lB1);
                Al[2] = pack_bf2(lA2, lA3);
                Al[3] = pack_bf2(lB2, lB3);
            }

#pragma unroll
            for (int nt = 0; nt < NTILES; nt++) {
                uint4 q = Bs4[(nt * 4 + ks) * 32 + lane];
                mma16816(C[nt], Ah, q.x, q.y);   // hi * hi
                mma16816(C[nt], Ah, q.z, q.w);   // hi * lo
                mma16816(C[nt], Al, q.x, q.y);   // lo * hi
            }
        }

        float vA = 0.f, vB = 0.f;
#pragma unroll
        for (int nt = 0; nt < 8; nt++) {
            vA = fmaf(C[nt][0], C[nt][0], vA);
            vA = fmaf(C[nt][1], C[nt][1], vA);
            vB = fmaf(C[nt][2], C[nt][2], vB);
            vB = fmaf(C[nt][3], C[nt][3], vB);
        }
        vA += __shfl_xor_sync(0xFFFFFFFFu, vA, 1);
        vA += __shfl_xor_sync(0xFFFFFFFFu, vA, 2);
        vB += __shfl_xor_sync(0xFFFFFFFFu, vB, 1);
        vB += __shfl_xor_sync(0xFFFFFFFFu, vB, 2);

        if (t == 0) {
            outL[pA] = C[8][0];
            outL[pB] = C[8][2];
            outV[pA] = vA;
            outV[pB] = vB;
        }
    }
}

// ---------------------------------------------------------------------------
extern "C" void kernel_launch(void* const* d_in, const int* in_sizes, int n_in,
                              void* d_out, int out_size)
{
    const float* bases   = (const float*)d_in[0];
    const float* targets = (const float*)d_in[1];
    if (n_in >= 2 && in_sizes[0] < in_sizes[1]) {
        const float* t = bases; bases = targets; targets = t;
    }
    float* out = (float*)d_out;

    stats_kernel<<<BATCH * NBLK, 256>>>(bases, targets);
    reduce_kernel<<<BATCH * 16, 256>>>();
    solve_kernel<<<BATCH, 256>>>(out);
    pred_mma_kernel<<<BATCH * PRED_CTAS, 256>>>(bases, out);
}

// round 16
// speedup vs baseline: 1.7311x; 1.1020x over previous
#include <cuda_runtime.h>
#include <cuda_bf16.h>
#include <math.h>
#include <stdint.h>

// Problem constants
#define BATCH 8
#define MCH   63
#define HW    307200
#define NBLK  150         // stats blocks per batch
#define CHUNK 2048        // HW / NBLK
#define SUB   2048        // single scan per block
#define NSUB  1
#define PPT   8           // 256*8 = 2048
#define NV    16

// pred mma constants
#define NTILES     9
#define KSTEPS     4
#define BFRAG_SZ   (NTILES * KSTEPS * 32 * 4)   // u32 per batch = 4608
#define PRED_CTAS  150     // per batch; 150 * 2048 px = HW
#define PX_PER_CTA 2048
#define ROUNDS     16      // 2048 / (8 warps * 16 px)

// Scratch (device globals; no allocation allowed)
__device__ float    g_partA[BATCH * NBLK * 4096];
__device__ float    g_partX[BATCH * NBLK * 64];
__device__ float    g_partS[BATCH * NBLK * 2];
__device__ float    g_redA[BATCH * 4096];
__device__ float    g_redX[BATCH * 64];
__device__ float    g_redS[BATCH * 2];
__device__ uint32_t g_bfrag[BATCH * BFRAG_SZ];

// ---------------- small helpers ----------------
__device__ __forceinline__ uint32_t pack_bf2(float lo_elem, float hi_elem) {
    uint32_t r;
    asm("cvt.rn.bf16x2.f32 %0, %1, %2;" : "=r"(r) : "f"(hi_elem), "f"(lo_elem));
    return r;
}
__device__ __forceinline__ void mma16816(float* c, const uint32_t* a, uint32_t b0, uint32_t b1) {
    asm volatile(
        "mma.sync.aligned.m16n8k16.row.col.f32.bf16.bf16.f32 "
        "{%0,%1,%2,%3}, {%4,%5,%6,%7}, {%8,%9}, {%0,%1,%2,%3};"
        : "+f"(c[0]), "+f"(c[1]), "+f"(c[2]), "+f"(c[3])
        : "r"(a[0]), "r"(a[1]), "r"(a[2]), "r"(a[3]), "r"(b0), "r"(b1));
}

// ---------------------------------------------------------------------------
// Kernel 1: sparse masked Gram accumulation (single scan, double-buffered).
// ---------------------------------------------------------------------------
__global__ void __launch_bounds__(256) stats_kernel(const float* __restrict__ bases,
                                                    const float* __restrict__ targets)
{
    const int b   = blockIdx.x / NBLK;
    const int blk = blockIdx.x % NBLK;
    const float* tgb = targets + (size_t)b * HW;
    const float* bs  = bases   + (size_t)b * MCH * HW;

    __shared__ int   pix [SUB];
    __shared__ float yls [SUB];
    __shared__ float bv  [2][NV][64];
    __shared__ float yg  [2][NV];
    __shared__ int   scan[256];

    const int tid = threadIdx.x;
    const int ti  = tid >> 4;
    const int tj  = tid & 15;

    float acc[4][4];
#pragma unroll
    for (int i = 0; i < 4; i++)
#pragma unroll
        for (int j = 0; j < 4; j++) acc[i][j] = 0.f;

    float xty = 0.f, yty = 0.f, ncnt = 0.f;

    {
        const int base = blk * CHUNK;
        const int p0   = base + tid * PPT;

        int cnt = 0;
#pragma unroll
        for (int k = 0; k < PPT; k++) {
            float y = tgb[p0 + k];
            if (isfinite(y)) cnt++;
        }
        scan[tid] = cnt;
        __syncthreads();
        for (int off = 1; off < 256; off <<= 1) {
            int v = (tid >= off) ? scan[tid - off] : 0;
            __syncthreads();
            scan[tid] += v;
            __syncthreads();
        }
        int wo    = scan[tid] - cnt;
        int total = scan[255];
        __syncthreads();

#pragma unroll
        for (int k = 0; k < PPT; k++) {
            float y = tgb[p0 + k];
            if (isfinite(y)) { pix[wo] = p0 + k; yls[wo] = y; wo++; }
        }
        __syncthreads();

        if (tid == 0) ncnt += (float)total;

        const int ng = (total + NV - 1) / NV;

        if (ng > 0) {
#pragma unroll
            for (int r = 0; r < 4; r++) {
                int idx = r * 256 + tid;
                int v = idx >> 6, c = idx & 63;
                float val = 0.f;
                if (v < total)
                    val = (c == 0) ? 1.f : bs[(size_t)(c - 1) * HW + pix[v]];
                bv[0][v][c] = val;
            }
            if (tid < NV) yg[0][tid] = (tid < total) ? yls[tid] : 0.f;
        }
        __syncthreads();

        for (int g = 0; g < ng; g++) {
            const int cur = g & 1;
            if (g + 1 < ng) {
                const int nxt = cur ^ 1;
                const int bnv = (g + 1) * NV;
#pragma unroll
                for (int r = 0; r < 4; r++) {
                    int idx = r * 256 + tid;
                    int v = idx >> 6, c = idx & 63;
                    int gv = bnv + v;
                    float val = 0.f;
                    if (gv < total)
                        val = (c == 0) ? 1.f : bs[(size_t)(c - 1) * HW + pix[gv]];
                    bv[nxt][v][c] = val;
                }
                if (tid < NV) {
                    int gv = bnv + tid;
                    yg[nxt][tid] = (gv < total) ? yls[gv] : 0.f;
                }
            }

            const float4* bv4 = (const float4*)bv[cur];
#pragma unroll
            for (int v = 0; v < NV; v++) {
                float4 R = bv4[v * 16 + ti];
                float4 C = bv4[v * 16 + tj];
                acc[0][0] += R.x * C.x; acc[0][1] += R.x * C.y; acc[0][2] += R.x * C.z; acc[0][3] += R.x * C.w;
                acc[1][0] += R.y * C.x; acc[1][1] += R.y * C.y; acc[1][2] += R.y * C.z; acc[1][3] += R.y * C.w;
                acc[2][0] += R.z * C.x; acc[2][1] += R.z * C.y; acc[2][2] += R.z * C.z; acc[2][3] += R.z * C.w;
                acc[3][0] += R.w * C.x; acc[3][1] += R.w * C.y; acc[3][2] += R.w * C.z; acc[3][3] += R.w * C.w;
            }
            if (tid < 64) {
#pragma unroll
                for (int v = 0; v < NV; v++) xty += bv[cur][v][tid] * yg[cur][v];
            }
            if (tid == 64) {
#pragma unroll
                for (int v = 0; v < NV; v++) yty += yg[cur][v] * yg[cur][v];
            }
            __syncthreads();
        }
    }

    float* pa = g_partA + ((size_t)b * NBLK + blk) * 4096;
#pragma unroll
    for (int i = 0; i < 4; i++)
#pragma unroll
        for (int j = 0; j < 4; j++)
            pa[(ti * 4 + i) * 64 + (tj * 4 + j)] = acc[i][j];
    if (tid < 64)  g_partX[((size_t)b * NBLK + blk) * 64 + tid] = xty;
    if (tid == 64) g_partS[((size_t)b * NBLK + blk) * 2 + 0] = yty;
    if (tid == 0)  g_partS[((size_t)b * NBLK + blk) * 2 + 1] = ncnt;
}

// ---------------------------------------------------------------------------
// Kernel 1.5: parallel partial reduction.
// ---------------------------------------------------------------------------
__global__ void __launch_bounds__(256) reduce_kernel()
{
    const int b    = blockIdx.x >> 4;
    const int part = blockIdx.x & 15;
    const int e    = part * 256 + threadIdx.x;

    const float* pa = g_partA + (size_t)b * NBLK * 4096 + e;
    float s = 0.f;
#pragma unroll 10
    for (int k = 0; k < NBLK; k++) s += pa[(size_t)k * 4096];
    g_redA[b * 4096 + e] = s;

    if (part == 0 && threadIdx.x < 64) {
        const float* px = g_partX + (size_t)b * NBLK * 64 + threadIdx.x;
        float sx = 0.f;
#pragma unroll 10
        for (int k = 0; k < NBLK; k++) sx += px[(size_t)k * 64];
        g_redX[b * 64 + threadIdx.x] = sx;
    }
    if (part == 1 && threadIdx.x < 2) {
        const float* ps = g_partS + (size_t)b * NBLK * 2 + threadIdx.x;
        float ss = 0.f;
#pragma unroll 10
        for (int k = 0; k < NBLK; k++) ss += ps[(size_t)k * 2];
        g_redS[b * 2 + threadIdx.x] = ss;
    }
}

// ---------------------------------------------------------------------------
// Kernel 2: Cholesky + solves + beta + L^-1 + B-fragment table.
// ---------------------------------------------------------------------------
__global__ void __launch_bounds__(256) solve_kernel(float* __restrict__ out)
{
    const int b   = blockIdx.x;
    const int tid = threadIdx.x;

    __shared__ float A [64 * 65];
    __shared__ float Li[64 * 65];
    __shared__ float xty[64], wv[64], zv[64];
    __shared__ float sc[4];

    for (int e = tid; e < 4096; e += 256)
        A[(e >> 6) * 65 + (e & 63)] = g_redA[b * 4096 + e];
    if (tid < 64) xty[tid] = g_redX[b * 64 + tid];
    if (tid == 0) { sc[0] = g_redS[b * 2 + 0]; sc[1] = g_redS[b * 2 + 1]; }
    __syncthreads();

    for (int k = 0; k < 64; k++) {
        if (tid == 0) A[k * 65 + k] = sqrtf(A[k * 65 + k]);
        __syncthreads();
        if (tid > k && tid < 64) A[tid * 65 + k] /= A[k * 65 + k];
        __syncthreads();
        if (tid > k && tid < 64) {
            float l = A[tid * 65 + k];
            for (int i = k + 1; i <= tid; i++) A[tid * 65 + i] -= l * A[i * 65 + k];
        }
        __syncthreads();
    }

    if (tid < 64) zv[tid] = xty[tid];
    __syncthreads();
    for (int k = 0; k < 64; k++) {
        if (tid == k) zv[k] /= A[k * 65 + k];
        __syncthreads();
        if (tid > k && tid < 64) zv[tid] -= A[tid * 65 + k] * zv[k];
        __syncthreads();
    }
    if (tid < 64) wv[tid] = zv[tid];
    __syncthreads();
    for (int k = 63; k >= 0; k--) {
        if (tid == k) wv[k] /= A[k * 65 + k];
        __syncthreads();
        if (tid < k) wv[tid] -= A[k * 65 + tid] * wv[k];
        __syncthreads();
    }

    if (tid == 0) {
        float yt = sc[0], n = sc[1];
        float wx = 0.f, zz = 0.f;
        for (int c = 0; c < 64; c++) { wx += wv[c] * xty[c]; zz += zv[c] * zv[c]; }
        float E = yt - 2.f * wx + zz;
        float beta0 = sqrtf(n), beta = beta0;
        bool done = false;
        for (int it = 0; it < 5; it++) {
            float bn   = n / (E + 64.f / beta);
            bool  conv = fabsf(bn / beta0 - 1.f) < 0.02f;
            if (!done) { beta = bn; beta0 = bn; }
            done = done || conv;
        }
        sc[2] = beta;
    }
    __syncthreads();

    if (tid < 64) {
        const int c = tid;
        for (int k = c; k < 64; k++) {
            float s = (k == c) ? 1.f : 0.f;
            for (int j = c; j < k; j++) s -= A[k * 65 + j] * Li[j * 65 + c];
            Li[k * 65 + c] = s / A[k * 65 + k];
        }
    }
    __syncthreads();

    const float sb = rsqrtf(sc[2]);
    if (tid < 64) out[(size_t)BATCH * HW + (size_t)b * 64 + tid] = wv[tid];

    uint32_t* tabb = g_bfrag + (size_t)b * BFRAG_SZ;
    for (int e = tid; e < BFRAG_SZ; e += 256) {
        int j    = e & 3;
        int lane = (e >> 2) & 31;
        int ks   = (e >> 7) & 3;
        int nt   = e >> 9;
        int n    = nt * 8 + (lane >> 2);
        int k0   = ks * 16 + (lane & 3) * 2 + ((j & 1) ? 8 : 0);

        float v0, v1;
        if (n < 64) {
            v0 = (k0     <= n) ? Li[n * 65 + k0]     * sb : 0.f;
            v1 = (k0 + 1 <= n) ? Li[n * 65 + k0 + 1] * sb : 0.f;
        } else if (n == 64) {
            v0 = wv[k0]; v1 = wv[k0 + 1];
        } else {
            v0 = 0.f; v1 = 0.f;
        }
        uint32_t r;
        if ((j >> 1) == 0) {
            r = pack_bf2(v0, v1);
        } else {
            float h0 = __bfloat162float(__float2bfloat16(v0));
            float h1 = __bfloat162float(__float2bfloat16(v1));
            r = pack_bf2(v0 - h0, v1 - h1);
        }
        tabb[e] = r;
    }
}

// ---------------------------------------------------------------------------
// Kernel 3: pred + var, nt-OUTER restructure.
// All 4 K-steps of A fragments loaded up front (MLP=32). Then each var
// row-tile accumulates into 4 REUSED C registers over its triangular K range
// (zero tiles skipped by literal bounds) and squares immediately into vA/vB.
// Live regs: frag 32 + C 4 + W 4 + misc  -> 4 CTAs/SM.
// ---------------------------------------------------------------------------
#define VAR_TILE(NT, KSMAX) do {                                             \
    float C[4] = {0.f, 0.f, 0.f, 0.f};                                       \
    _Pragma("unroll")                                                        \
    for (int ks = 0; ks < (KSMAX); ks++) {                                   \
        uint4 q = Bs4[((NT) * 4 + ks) * 32 + lane];                          \
        mma16816(C, Ah[ks], q.x, q.y);                                       \
        mma16816(C, Ah[ks], q.z, q.w);                                       \
        mma16816(C, Al[ks], q.x, q.y);                                       \
    }                                                                        \
    vA = fmaf(C[0], C[0], vA); vA = fmaf(C[1], C[1], vA);                    \
    vB = fmaf(C[2], C[2], vB); vB = fmaf(C[3], C[3], vB);                    \
} while (0)

__global__ void __launch_bounds__(256, 4) pred_mma_kernel(const float* __restrict__ bases,
                                                          float* __restrict__ out)
{
    __shared__ uint32_t Bsm[BFRAG_SZ];   // 18.4 KB

    const int b    = blockIdx.x / PRED_CTAS;
    const int cta  = blockIdx.x % PRED_CTAS;
    const int tid  = threadIdx.x;
    const int wid  = tid >> 5;
    const int lane = tid & 31;
    const int g    = lane >> 2;
    const int t    = lane & 3;

    {
        const uint32_t* src = g_bfrag + (size_t)b * BFRAG_SZ;
        for (int e = tid; e < BFRAG_SZ; e += 256) Bsm[e] = src[e];
    }
    __syncthreads();
    const uint4* Bs4 = (const uint4*)Bsm;

    const float* bs   = bases + (size_t)b * MCH * HW;
    float* outL = out + (size_t)b * HW;
    float* outV = out + (size_t)BATCH * HW + (size_t)BATCH * 64 + (size_t)b * HW;

    for (int r = 0; r < ROUNDS; r++) {
        const int px0 = cta * PX_PER_CTA + r * 128 + wid * 16;
        const int pA  = px0 + g;
        const int pB  = pA + 8;

        // ---- all A fragments up front (32 coalesced LDGs, MLP 32) ----
        uint32_t Ah[KSTEPS][4], Al[KSTEPS][4];
#pragma unroll
        for (int ks = 0; ks < KSTEPS; ks++) {
            const int cA = ks * 16 + t * 2;

            float fA0 = (cA == 0) ? 1.f : __ldg(bs + (size_t)(cA - 1) * HW + pA);
            float fA1 = __ldg(bs + (size_t)(cA    ) * HW + pA);
            float fA2 = __ldg(bs + (size_t)(cA + 7) * HW + pA);
            float fA3 = __ldg(bs + (size_t)(cA + 8) * HW + pA);
            float fB0 = (cA == 0) ? 1.f : __ldg(bs + (size_t)(cA - 1) * HW + pB);
            float fB1 = __ldg(bs + (size_t)(cA    ) * HW + pB);
            float fB2 = __ldg(bs + (size_t)(cA + 7) * HW + pB);
            float fB3 = __ldg(bs + (size_t)(cA + 8) * HW + pB);

            Ah[ks][0] = pack_bf2(fA0, fA1);
            Ah[ks][1] = pack_bf2(fB0, fB1);
            Ah[ks][2] = pack_bf2(fA2, fA3);
            Ah[ks][3] = pack_bf2(fB2, fB3);
            float h;
            h = __uint_as_float(Ah[ks][0] << 16);          float lA0 = fA0 - h;
            h = __uint_as_float(Ah[ks][0] & 0xFFFF0000u);  float lA1 = fA1 - h;
            h = __uint_as_float(Ah[ks][1] << 16);          float lB0 = fB0 - h;
            h = __uint_as_float(Ah[ks][1] & 0xFFFF0000u);  float lB1 = fB1 - h;
            h = __uint_as_float(Ah[ks][2] << 16);          float lA2 = fA2 - h;
            h = __uint_as_float(Ah[ks][2] & 0xFFFF0000u);  float lA3 = fA3 - h;
            h = __uint_as_float(Ah[ks][3] << 16);          float lB2 = fB2 - h;
            h = __uint_as_float(Ah[ks][3] & 0xFFFF0000u);  float lB3 = fB3 - h;
            Al[ks][0] = pack_bf2(lA0, lA1);
            Al[ks][1] = pack_bf2(lB0, lB1);
            Al[ks][2] = pack_bf2(lA2, lA3);
            Al[ks][3] = pack_bf2(lB2, lB3);
        }

        // ---- variance tiles: C regs reused, triangular K bounds ----
        float vA = 0.f, vB = 0.f;
        VAR_TILE(0, 1);
        VAR_TILE(1, 1);
        VAR_TILE(2, 2);
        VAR_TILE(3, 2);
        VAR_TILE(4, 3);
        VAR_TILE(5, 3);
        VAR_TILE(6, 4);
        VAR_TILE(7, 4);

        // ---- w tile (prediction), full K ----
        float W[4] = {0.f, 0.f, 0.f, 0.f};
#pragma unroll
        for (int ks = 0; ks < KSTEPS; ks++) {
            uint4 q = Bs4[(8 * 4 + ks) * 32 + lane];
            mma16816(W, Ah[ks], q.x, q.y);
            mma16816(W, Ah[ks], q.z, q.w);
            mma16816(W, Al[ks], q.x, q.y);
        }

        vA += __shfl_xor_sync(0xFFFFFFFFu, vA, 1);
        vA += __shfl_xor_sync(0xFFFFFFFFu, vA, 2);
        vB += __shfl_xor_sync(0xFFFFFFFFu, vB, 1);
        vB += __shfl_xor_sync(0xFFFFFFFFu, vB, 2);

        if (t == 0) {
            outL[pA] = W[0];
            outL[pB] = W[2];
            outV[pA] = vA;
            outV[pB] = vB;
        }
    }
}

// ---------------------------------------------------------------------------
extern "C" void kernel_launch(void* const* d_in, const int* in_sizes, int n_in,
                              void* d_out, int out_size)
{
    const float* bases   = (const float*)d_in[0];
    const float* targets = (const float*)d_in[1];
    if (n_in >= 2 && in_sizes[0] < in_sizes[1]) {
        const float* t = bases; bases = targets; targets = t;
    }
    float* out = (float*)d_out;

    stats_kernel<<<BATCH * NBLK, 256>>>(bases, targets);
    reduce_kernel<<<BATCH * 16, 256>>>();
    solve_kernel<<<BATCH, 256>>>(out);
    pred_mma_kernel<<<BATCH * PRED_CTAS, 256>>>(bases, out);
}